// round 1
// baseline (speedup 1.0000x reference)
#include <cuda_runtime.h>
#include <math.h>

#define N_NODES 200000
#define N_EDGES 3200000

typedef unsigned long long u64;

// ---------------- static scratch (no dynamic allocation allowed) ----------------
__device__ int   g_count [N_NODES];
__device__ int   g_rowptr[N_NODES];
__device__ int   g_cursor[N_NODES];
__device__ int   g_bsums [256];
__device__ int   g_ssrc  [N_EDGES];
__device__ float g_skw0  [N_EDGES];
__device__ float g_skw1  [N_EDGES];
__device__ float g_agg0  [N_NODES * 16];
__device__ float g_h     [N_NODES * 32];
__device__ float g_agg1  [N_NODES * 64];

// ---------------- packed f32x2 helpers ----------------
__device__ __forceinline__ u64 splat2(float x) {
    u64 r; unsigned xi = __float_as_uint(x);
    asm("mov.b64 %0, {%1, %1};" : "=l"(r) : "r"(xi));
    return r;
}
__device__ __forceinline__ void ffma2(u64& d, u64 a, u64 b) {
    asm("fma.rn.f32x2 %0, %1, %2, %0;" : "+l"(d) : "l"(a), "l"(b));
}

// ---------------- CSR build ----------------
__global__ void k_init() {
    int i = blockIdx.x * blockDim.x + threadIdx.x;
    if (i < N_NODES) g_count[i] = 0;
}

__global__ void k_hist(const int* __restrict__ dst) {
    int e = blockIdx.x * blockDim.x + threadIdx.x;
    if (e < N_EDGES) atomicAdd(&g_count[dst[e]], 1);
}

__global__ void k_scan1() {
    __shared__ int s[1024];
    int tid = threadIdx.x;
    int i = blockIdx.x * 1024 + tid;
    int v = (i < N_NODES) ? g_count[i] : 0;
    s[tid] = v;
    __syncthreads();
    for (int d = 1; d < 1024; d <<= 1) {
        int t = (tid >= d) ? s[tid - d] : 0;
        __syncthreads();
        s[tid] += t;
        __syncthreads();
    }
    if (i < N_NODES) g_rowptr[i] = s[tid] - v;   // block-local exclusive
    if (tid == 1023) g_bsums[blockIdx.x] = s[1023];
}

__global__ void k_scan2(int nb) {
    __shared__ int s[256];
    int tid = threadIdx.x;
    s[tid] = (tid < nb) ? g_bsums[tid] : 0;
    __syncthreads();
    if (tid == 0) {
        int run = 0;
        for (int i = 0; i < nb; i++) { int v = s[i]; s[i] = run; run += v; }
    }
    __syncthreads();
    if (tid < nb) g_bsums[tid] = s[tid];
}

__global__ void k_scan3() {
    int i = blockIdx.x * blockDim.x + threadIdx.x;
    if (i < N_NODES) {
        int v = g_rowptr[i] + g_bsums[i >> 10];
        g_rowptr[i] = v;
        g_cursor[i] = v;
    }
}

__global__ void k_scatter(const int* __restrict__ src, const int* __restrict__ dst,
                          const float* __restrict__ kw) {
    int e = blockIdx.x * blockDim.x + threadIdx.x;
    if (e < N_EDGES) {
        int t = dst[e];
        int p = atomicAdd(&g_cursor[t], 1);
        g_ssrc[p] = src[e];
        g_skw0[p] = kw[e];
        g_skw1[p] = kw[N_EDGES + e];
    }
}

// ---------------- layer 0 conv: warp per node, 8 lanes/edge, 4 edges at a time ----------------
__global__ void k_conv0(const float* __restrict__ x) {
    int warp = threadIdx.x >> 5, lane = threadIdx.x & 31;
    int node = blockIdx.x * 8 + warp;
    int f = lane & 7, sub = lane >> 3;
    int start = g_rowptr[node], cnt = g_count[node], end = start + cnt;
    float a0 = 0.f, a1 = 0.f;
    int e = start;
    for (; e + 4 <= end; e += 4) {
        int s    = g_ssrc[e + sub];
        float k0 = g_skw0[e + sub], k1 = g_skw1[e + sub];
        float v  = __ldg(&x[s * 8 + f]);
        a0 = fmaf(k0, v, a0);
        a1 = fmaf(k1, v, a1);
    }
    if (e + sub < end) {
        int s    = g_ssrc[e + sub];
        float k0 = g_skw0[e + sub], k1 = g_skw1[e + sub];
        float v  = __ldg(&x[s * 8 + f]);
        a0 = fmaf(k0, v, a0);
        a1 = fmaf(k1, v, a1);
    }
    // reduce across the 4 edge sub-lanes (lane bits 3,4)
    a0 += __shfl_xor_sync(0xffffffffu, a0, 8);
    a0 += __shfl_xor_sync(0xffffffffu, a0, 16);
    a1 += __shfl_xor_sync(0xffffffffu, a1, 8);
    a1 += __shfl_xor_sync(0xffffffffu, a1, 16);
    if (lane < 8)        g_agg0[node * 16 + f]     = a0;
    else if (lane < 16)  g_agg0[node * 16 + 8 + f] = a1;
}

// ---------------- layer 0 MLP + L2 norm: thread per node ----------------
__global__ void k_mlp0(const float* __restrict__ W0, const float* __restrict__ b0) {
    __shared__ float W0s[512];
    __shared__ float b0s[32];
    int tid = threadIdx.x;
    W0s[tid] = W0[tid];
    W0s[tid + 256] = W0[tid + 256];
    if (tid < 32) b0s[tid] = b0[tid];
    __syncthreads();
    int t = blockIdx.x * 256 + tid;
    if (t >= N_NODES) return;

    float a[16];
    const float4* ag = (const float4*)(g_agg0 + t * 16);
#pragma unroll
    for (int i = 0; i < 4; i++) {
        float4 v = ag[i];
        a[4*i] = v.x; a[4*i+1] = v.y; a[4*i+2] = v.z; a[4*i+3] = v.w;
    }
    float acc[32];
#pragma unroll
    for (int j = 0; j < 32; j++) acc[j] = b0s[j];
#pragma unroll
    for (int k = 0; k < 16; k++) {
        float ak = a[k];
        const float4* w = (const float4*)(W0s + k * 32);
#pragma unroll
        for (int q = 0; q < 8; q++) {
            float4 wv = w[q];
            acc[4*q]   = fmaf(ak, wv.x, acc[4*q]);
            acc[4*q+1] = fmaf(ak, wv.y, acc[4*q+1]);
            acc[4*q+2] = fmaf(ak, wv.z, acc[4*q+2]);
            acc[4*q+3] = fmaf(ak, wv.w, acc[4*q+3]);
        }
    }
    float ss = 0.f;
#pragma unroll
    for (int j = 0; j < 32; j++) ss = fmaf(acc[j], acc[j], ss);
    float sc = 1.f / fmaxf(sqrtf(ss), 1e-12f);
    float4* hp = (float4*)(g_h + t * 32);
#pragma unroll
    for (int q = 0; q < 8; q++) {
        float4 v;
        v.x = acc[4*q] * sc; v.y = acc[4*q+1] * sc;
        v.z = acc[4*q+2] * sc; v.w = acc[4*q+3] * sc;
        hp[q] = v;
    }
}

// ---------------- layer 1 conv: warp per node, lane = feature, 4-edge unroll ----------------
__global__ void k_conv1() {
    int warp = threadIdx.x >> 5, lane = threadIdx.x & 31;
    int node = blockIdx.x * 8 + warp;
    int start = g_rowptr[node], cnt = g_count[node], end = start + cnt;
    float a0 = 0.f, a1 = 0.f;
    const float* __restrict__ h = g_h;
    int e = start;
    for (; e + 4 <= end; e += 4) {
        int s0 = g_ssrc[e], s1 = g_ssrc[e+1], s2 = g_ssrc[e+2], s3 = g_ssrc[e+3];
        float v0 = h[s0*32 + lane], v1 = h[s1*32 + lane];
        float v2 = h[s2*32 + lane], v3 = h[s3*32 + lane];
        float k00 = g_skw0[e], k01 = g_skw0[e+1], k02 = g_skw0[e+2], k03 = g_skw0[e+3];
        float k10 = g_skw1[e], k11 = g_skw1[e+1], k12 = g_skw1[e+2], k13 = g_skw1[e+3];
        a0 = fmaf(k00, v0, a0); a0 = fmaf(k01, v1, a0);
        a0 = fmaf(k02, v2, a0); a0 = fmaf(k03, v3, a0);
        a1 = fmaf(k10, v0, a1); a1 = fmaf(k11, v1, a1);
        a1 = fmaf(k12, v2, a1); a1 = fmaf(k13, v3, a1);
    }
    for (; e < end; ++e) {
        int s = g_ssrc[e];
        float v = h[s*32 + lane];
        a0 = fmaf(g_skw0[e], v, a0);
        a1 = fmaf(g_skw1[e], v, a1);
    }
    g_agg1[node*64 + lane]      = a0;
    g_agg1[node*64 + 32 + lane] = a1;
}

// ---------------- layer 1 MLP (64 -> relu 128 -> 64) + L2 norm, f32x2 packed ----------------
// dynamic smem layout in floats:
#define SM_W1 0
#define SM_W2 8192
#define SM_AZ 16384            // A: 64 x stride-129 (8256 f); reused as Z pairs u64[32*128]
#define SM_B1 (16384 + 8256)
#define SM_B2 (SM_B1 + 128)
#define SM_TOTAL (SM_B2 + 64)  // floats

__global__ void __launch_bounds__(128, 1)
k_mlp1(const float* __restrict__ W1, const float* __restrict__ b1,
       const float* __restrict__ W2, const float* __restrict__ b2,
       float* __restrict__ out) {
    extern __shared__ float sm[];
    int tid = threadIdx.x;
    for (int i = tid; i < 8192; i += 128) {
        sm[SM_W1 + i] = W1[i];
        sm[SM_W2 + i] = W2[i];
    }
    sm[SM_B1 + tid] = b1[tid];
    if (tid < 64) sm[SM_B2 + tid] = b2[tid];

    int base = blockIdx.x * 128;   // first node of this block
    for (int idx = tid; idx < 8192; idx += 128) {
        int g = base * 64 + idx;
        float v = (g < N_NODES * 64) ? g_agg1[g] : 0.f;
        int k = idx & 63, nl = idx >> 6;
        sm[SM_AZ + k * 129 + nl] = v;
    }
    __syncthreads();

    // mm1: z[128] = a[64] @ W1 + b1   (acc = 64 packed pairs)
    u64 acc[64];
    const u64* b1v = (const u64*)(sm + SM_B1);
#pragma unroll
    for (int p = 0; p < 64; p++) acc[p] = b1v[p];
    const float* As = sm + SM_AZ;
    for (int k = 0; k < 64; k++) {
        u64 ak2 = splat2(As[k * 129 + tid]);
        const ulonglong2* w = (const ulonglong2*)(sm + SM_W1 + k * 128);
#pragma unroll
        for (int q = 0; q < 32; q++) {
            ulonglong2 wv = w[q];
            ffma2(acc[2*q],   ak2, wv.x);
            ffma2(acc[2*q+1], ak2, wv.y);
        }
    }
    // relu
#pragma unroll
    for (int p = 0; p < 64; p++) {
        float lo = __uint_as_float((unsigned)acc[p]);
        float hi = __uint_as_float((unsigned)(acc[p] >> 32));
        lo = fmaxf(lo, 0.f);
        hi = fmaxf(hi, 0.f);
        acc[p] = ((u64)__float_as_uint(hi) << 32) | (u64)__float_as_uint(lo);
    }

    // mm2: o[64] = z[128] @ W2 + b2, staged through smem in two halves
    u64 outp[32];
    const u64* b2v = (const u64*)(sm + SM_B2);
#pragma unroll
    for (int q = 0; q < 32; q++) outp[q] = b2v[q];

    u64* Z2 = (u64*)(sm + SM_AZ);
#pragma unroll
    for (int half = 0; half < 2; half++) {
        __syncthreads();
#pragma unroll
        for (int p = 0; p < 32; p++) Z2[p * 128 + tid] = acc[half * 32 + p];
        __syncthreads();
        for (int p = 0; p < 32; p++) {
            u64 z2 = Z2[p * 128 + tid];
            u64 zl = splat2(__uint_as_float((unsigned)z2));
            u64 zh = splat2(__uint_as_float((unsigned)(z2 >> 32)));
            int k0 = half * 64 + 2 * p;
            const ulonglong2* r0 = (const ulonglong2*)(sm + SM_W2 + k0 * 64);
            const ulonglong2* r1 = (const ulonglong2*)(sm + SM_W2 + (k0 + 1) * 64);
#pragma unroll
            for (int q = 0; q < 16; q++) {
                ulonglong2 w0 = r0[q];
                ffma2(outp[2*q],   zl, w0.x);
                ffma2(outp[2*q+1], zl, w0.y);
            }
#pragma unroll
            for (int q = 0; q < 16; q++) {
                ulonglong2 w1 = r1[q];
                ffma2(outp[2*q],   zh, w1.x);
                ffma2(outp[2*q+1], zh, w1.y);
            }
        }
    }

    // L2 normalize + store
    float o[64];
    float ss = 0.f;
#pragma unroll
    for (int q = 0; q < 32; q++) {
        float lo = __uint_as_float((unsigned)outp[q]);
        float hi = __uint_as_float((unsigned)(outp[q] >> 32));
        o[2*q] = lo; o[2*q+1] = hi;
        ss = fmaf(lo, lo, ss);
        ss = fmaf(hi, hi, ss);
    }
    int node = base + tid;
    if (node < N_NODES) {
        float sc = 1.f / fmaxf(sqrtf(ss), 1e-12f);
        float4* op = (float4*)(out + node * 64);
#pragma unroll
        for (int q = 0; q < 16; q++) {
            float4 v;
            v.x = o[4*q] * sc;   v.y = o[4*q+1] * sc;
            v.z = o[4*q+2] * sc; v.w = o[4*q+3] * sc;
            op[q] = v;
        }
    }
}

// ---------------- launch ----------------
extern "C" void kernel_launch(void* const* d_in, const int* in_sizes, int n_in,
                              void* d_out, int out_size) {
    const float* x  = (const float*)d_in[0];
    const int*   ei = (const int*)  d_in[1];
    const float* kw = (const float*)d_in[2];
    const float* W0 = (const float*)d_in[3];
    const float* b0 = (const float*)d_in[4];
    const float* W1 = (const float*)d_in[5];
    const float* b1 = (const float*)d_in[6];
    const float* W2 = (const float*)d_in[7];
    const float* b2 = (const float*)d_in[8];
    float* out = (float*)d_out;
    const int* src = ei;
    const int* dst = ei + N_EDGES;

    cudaFuncSetAttribute(k_mlp1, cudaFuncAttributeMaxDynamicSharedMemorySize,
                         SM_TOTAL * (int)sizeof(float));

    k_init   <<<(N_NODES + 255) / 256, 256>>>();
    k_hist   <<<(N_EDGES + 255) / 256, 256>>>(dst);
    k_scan1  <<<(N_NODES + 1023) / 1024, 1024>>>();
    k_scan2  <<<1, 256>>>((N_NODES + 1023) / 1024);
    k_scan3  <<<(N_NODES + 255) / 256, 256>>>();
    k_scatter<<<(N_EDGES + 255) / 256, 256>>>(src, dst, kw);
    k_conv0  <<<N_NODES / 8, 256>>>(x);
    k_mlp0   <<<(N_NODES + 255) / 256, 256>>>(W0, b0);
    k_conv1  <<<N_NODES / 8, 256>>>();
    k_mlp1   <<<(N_NODES + 127) / 128, 128, SM_TOTAL * (int)sizeof(float)>>>(W1, b1, W2, b2, out);
}